// round 1
// baseline (speedup 1.0000x reference)
#include <cuda_runtime.h>
#include <cstdint>

// Problem constants (fixed shapes per reference)
#define NDIM 8192   // N_DIM  (reduction dim K)
#define DSK  1024   // D_SKETCH (output rows)
#define MC   4096   // M_COLS (output cols)

// 32 MB scratch for the folded cosine matrix C'[d,k] = cos(ang)*w[k]*D[k]
__device__ float g_C[(size_t)DSK * NDIM];

// ---------------------------------------------------------------------------
// Kernel 1: build C' — must replicate the reference's fp32 rounding exactly:
//   ang = fl32( fl32( fl32(pi/16384) * (2n+1) ) * k ),  then cos(ang)
// ---------------------------------------------------------------------------
__global__ void build_C_kernel(const float* __restrict__ Dv,
                               const int* __restrict__ Pv) {
    const int d = blockIdx.y;
    const int k = blockIdx.x * blockDim.x + threadIdx.x;
    const int n = Pv[d];  // uniform per block -> broadcast load
    const float c0 = (float)(3.14159265358979323846 / 16384.0); // fl32(pi/(2N))
    float t   = c0 * (float)(2 * n + 1);   // fp32 round (2n+1 <= 16383 exact)
    float ang = t * (float)k;              // fp32 round (matches reference)
    float w   = (k == 0) ? 6.103515625e-05f : 1.220703125e-04f; // 0.5/8192, 1/8192 (exact)
    g_C[(size_t)d * NDIM + k] = cosf(ang) * w * Dv[k];
}

// ---------------------------------------------------------------------------
// Packed f32x2 FMA helpers (sm_100+; doubles fp32 fma-pipe throughput)
// ---------------------------------------------------------------------------
__device__ __forceinline__ unsigned long long bcast2(float x) {
    unsigned long long r;
    asm("mov.b64 %0, {%1, %1};" : "=l"(r) : "f"(x));
    return r;
}
__device__ __forceinline__ unsigned long long pair2(float x, float y) {
    unsigned long long r;
    asm("mov.b64 %0, {%1, %2};" : "=l"(r) : "f"(x), "f"(y));
    return r;
}
__device__ __forceinline__ void fma2(unsigned long long& d,
                                     unsigned long long a,
                                     unsigned long long b) {
    asm("fma.rn.f32x2 %0, %1, %2, %0;" : "+l"(d) : "l"(a), "l"(b));
}
__device__ __forceinline__ float2 unpack2(unsigned long long v) {
    float2 f;
    asm("mov.b64 {%0, %1}, %2;" : "=f"(f.x), "=f"(f.y) : "l"(v));
    return f;
}

// ---------------------------------------------------------------------------
// Kernel 2: out[1024,4096] = C'[1024,8192] @ M[8192,4096]   (all row-major)
// Block tile 128x128, K-tile 16, 256 threads, 8x8 microtile, double-buffered
// smem with register prefetch of the next K-tile.
// ---------------------------------------------------------------------------
#define BM 128
#define BN 128
#define BK 16

__global__ __launch_bounds__(256, 2)
void srft_gemm(const float* __restrict__ Bmat, float* __restrict__ out) {
    __shared__ float As[2][BK][BM];   // A stored transposed: As[k][row]
    __shared__ float Bs[2][BK][BN];

    const int tid = threadIdx.x;
    const int tx  = tid & 15;         // 0..15 -> 8 output cols each
    const int ty  = tid >> 4;         // 0..15 -> 8 output rows each
    const int n0  = blockIdx.x * BN;
    const int d0  = blockIdx.y * BM;

    // loader coordinates
    const int aRow = tid >> 2;        // 0..63 (two halves of 128 rows)
    const int aCol = (tid & 3) << 2;  // 0,4,8,12
    const int bRow = tid >> 5;        // 0..7  (two halves of 16 rows)
    const int bCol = (tid & 31) << 2; // 0..124

    const float* Aptr = g_C + (size_t)d0 * NDIM;
    const float* Bptr = Bmat + n0;

    // ---- load K-tile 0 into buffer 0 ----
    #pragma unroll
    for (int h = 0; h < 2; ++h) {
        int r = aRow + 64 * h;
        float4 v = *(const float4*)(Aptr + (size_t)r * NDIM + aCol);
        As[0][aCol + 0][r] = v.x;
        As[0][aCol + 1][r] = v.y;
        As[0][aCol + 2][r] = v.z;
        As[0][aCol + 3][r] = v.w;
    }
    #pragma unroll
    for (int h = 0; h < 2; ++h) {
        int r = bRow + 8 * h;
        *(float4*)&Bs[0][r][bCol] =
            *(const float4*)(Bptr + (size_t)r * MC + bCol);
    }
    __syncthreads();

    unsigned long long acc[8][4];
    #pragma unroll
    for (int i = 0; i < 8; ++i)
        #pragma unroll
        for (int j = 0; j < 4; ++j) acc[i][j] = 0ull;

    const int NT = NDIM / BK;  // 512 K-tiles
    int buf = 0;
    float4 pa[2], pb[2];

    for (int t = 0; t < NT; ++t) {
        // prefetch next K-tile into registers (hides GMEM latency under compute)
        if (t + 1 < NT) {
            const int k0 = (t + 1) * BK;
            #pragma unroll
            for (int h = 0; h < 2; ++h) {
                int r = aRow + 64 * h;
                pa[h] = *(const float4*)(Aptr + (size_t)r * NDIM + k0 + aCol);
            }
            #pragma unroll
            for (int h = 0; h < 2; ++h) {
                int r = bRow + 8 * h;
                pb[h] = *(const float4*)(Bptr + (size_t)(k0 + r) * MC + bCol);
            }
        }

        // ---- compute on current buffer ----
        #pragma unroll
        for (int kk = 0; kk < BK; ++kk) {
            float4 av0 = *(const float4*)&As[buf][kk][ty * 8];
            float4 av1 = *(const float4*)&As[buf][kk][ty * 8 + 4];
            float4 bv0 = *(const float4*)&Bs[buf][kk][tx * 8];
            float4 bv1 = *(const float4*)&Bs[buf][kk][tx * 8 + 4];
            unsigned long long b2[4] = {
                pair2(bv0.x, bv0.y), pair2(bv0.z, bv0.w),
                pair2(bv1.x, bv1.y), pair2(bv1.z, bv1.w)
            };
            float aa[8] = {av0.x, av0.y, av0.z, av0.w,
                           av1.x, av1.y, av1.z, av1.w};
            #pragma unroll
            for (int i = 0; i < 8; ++i) {
                unsigned long long a2 = bcast2(aa[i]);
                fma2(acc[i][0], a2, b2[0]);
                fma2(acc[i][1], a2, b2[1]);
                fma2(acc[i][2], a2, b2[2]);
                fma2(acc[i][3], a2, b2[3]);
            }
        }

        // ---- stage prefetched tile into the other buffer ----
        if (t + 1 < NT) {
            const int nb = buf ^ 1;
            #pragma unroll
            for (int h = 0; h < 2; ++h) {
                int r = aRow + 64 * h;
                As[nb][aCol + 0][r] = pa[h].x;
                As[nb][aCol + 1][r] = pa[h].y;
                As[nb][aCol + 2][r] = pa[h].z;
                As[nb][aCol + 3][r] = pa[h].w;
            }
            #pragma unroll
            for (int h = 0; h < 2; ++h) {
                int r = bRow + 8 * h;
                *(float4*)&Bs[nb][r][bCol] = pb[h];
            }
        }
        __syncthreads();
        buf ^= 1;
    }

    // ---- epilogue: 8x8 fp32 microtile -> GMEM, float4 stores ----
    float* optr = out + (size_t)(d0 + ty * 8) * MC + n0 + tx * 8;
    #pragma unroll
    for (int i = 0; i < 8; ++i) {
        float2 v0 = unpack2(acc[i][0]);
        float2 v1 = unpack2(acc[i][1]);
        float2 v2 = unpack2(acc[i][2]);
        float2 v3 = unpack2(acc[i][3]);
        *(float4*)(optr + (size_t)i * MC)     = make_float4(v0.x, v0.y, v1.x, v1.y);
        *(float4*)(optr + (size_t)i * MC + 4) = make_float4(v2.x, v2.y, v3.x, v3.y);
    }
}

// ---------------------------------------------------------------------------
// Launch: inputs in metadata order: M (f32 [8192,4096]), D (f32 [8192]),
//         P (i32 [1024]); output f32 [1024,4096] row-major.
// ---------------------------------------------------------------------------
extern "C" void kernel_launch(void* const* d_in, const int* in_sizes, int n_in,
                              void* d_out, int out_size) {
    const float* Mmat = (const float*)d_in[0];
    const float* Dv   = (const float*)d_in[1];
    const int*   Pv   = (const int*)d_in[2];
    float* out = (float*)d_out;

    build_C_kernel<<<dim3(NDIM / 256, DSK), 256>>>(Dv, Pv);
    srft_gemm<<<dim3(MC / BN, DSK / BM), 256>>>(Mmat, out);
}

// round 4
// speedup vs baseline: 1.9978x; 1.9978x over previous
#include <cuda_runtime.h>
#include <cuda_bf16.h>
#include <cstdint>

#define NDIM 8192   // K
#define DSK  1024   // output rows (M of GEMM)
#define MC   4096   // output cols (N of GEMM)

// ---------------- device scratch (allocation-free rule) ----------------------
__device__ __nv_bfloat16 g_Ahi[(size_t)DSK * NDIM];   // 16 MB
__device__ __nv_bfloat16 g_Alo[(size_t)DSK * NDIM];   // 16 MB
__device__ __nv_bfloat16 g_Bhi[(size_t)MC * NDIM];    // 64 MB (M^T, K-major)
__device__ __nv_bfloat16 g_Blo[(size_t)MC * NDIM];    // 64 MB

// ---------------- helpers ----------------------------------------------------
__device__ __forceinline__ uint32_t smem_u32(const void* p) {
    uint32_t a;
    asm("{ .reg .u64 t; cvta.to.shared.u64 t, %1; cvt.u32.u64 %0, t; }"
        : "=r"(a) : "l"(p));
    return a;
}
#define CP_ASYNC16(dst_u32, src_ptr) \
    asm volatile("cp.async.cg.shared.global [%0], [%1], 16;" \
                 :: "r"(dst_u32), "l"(src_ptr) : "memory")
#define CP_COMMIT() asm volatile("cp.async.commit_group;" ::: "memory")
#define CP_WAIT2()  asm volatile("cp.async.wait_group 2;" ::: "memory")

#define LDSM4(r0, r1, r2, r3, addr) \
    asm volatile("ldmatrix.sync.aligned.m8n8.x4.shared.b16 {%0,%1,%2,%3}, [%4];" \
                 : "=r"(r0), "=r"(r1), "=r"(r2), "=r"(r3) : "r"(addr))

#define MMA16816(c, a, b0, b1) \
    asm volatile("mma.sync.aligned.m16n8k16.row.col.f32.bf16.bf16.f32 " \
                 "{%0,%1,%2,%3}, {%4,%5,%6,%7}, {%8,%9}, {%0,%1,%2,%3};" \
                 : "+f"((c)[0]), "+f"((c)[1]), "+f"((c)[2]), "+f"((c)[3]) \
                 : "r"((a)[0]), "r"((a)[1]), "r"((a)[2]), "r"((a)[3]), \
                   "r"(b0), "r"(b1))

// ---------------------------------------------------------------------------
// Kernel 1: build C' = cos(ang)*w*D  (exact fp32 rounding order of reference)
// and split into bf16 hi/lo.
// ---------------------------------------------------------------------------
__global__ void build_AC(const float* __restrict__ Dv, const int* __restrict__ Pv) {
    const int d = blockIdx.y;
    const int k = blockIdx.x * blockDim.x + threadIdx.x;
    const int n = Pv[d];
    const float c0 = (float)(3.14159265358979323846 / 16384.0);
    float t   = c0 * (float)(2 * n + 1);
    float ang = t * (float)k;
    float w   = (k == 0) ? 6.103515625e-05f : 1.220703125e-04f;
    float c   = cosf(ang) * w * Dv[k];
    __nv_bfloat16 hi = __float2bfloat16(c);
    float lo = c - __bfloat162float(hi);
    size_t o = (size_t)d * NDIM + k;
    g_Ahi[o] = hi;
    g_Alo[o] = __float2bfloat16(lo);
}

// ---------------------------------------------------------------------------
// Kernel 2: transpose+convert M [8192,4096] f32 -> Bt_hi/lo [4096,8192] bf16
// ---------------------------------------------------------------------------
__global__ void conv_transpose(const float* __restrict__ Min) {
    __shared__ float tile[32][33];
    const int x0 = blockIdx.x * 32;  // n
    const int y0 = blockIdx.y * 32;  // k
    const int tx = threadIdx.x, ty = threadIdx.y;   // 32 x 8
    #pragma unroll
    for (int j = 0; j < 32; j += 8)
        tile[ty + j][tx] = Min[(size_t)(y0 + ty + j) * MC + x0 + tx];
    __syncthreads();
    #pragma unroll
    for (int j = 0; j < 32; j += 8) {
        float v = tile[tx][ty + j];
        __nv_bfloat16 hi = __float2bfloat16(v);
        float lo = v - __bfloat162float(hi);
        size_t o = (size_t)(x0 + ty + j) * NDIM + y0 + tx;
        g_Bhi[o] = hi;
        g_Blo[o] = __float2bfloat16(lo);
    }
}

// ---------------------------------------------------------------------------
// Kernel 3: GEMM via mma.sync bf16 (sm_80 path, runs on plain sm_100 target)
// out[1024,4096] = Ahi@Bhi + Ahi@Blo + Alo@Bhi   (fp32 accumulators)
// CTA 128x128, BK=32, 4-stage cp.async pipeline, 8 warps (4M x 2N), warp 32x64
// ---------------------------------------------------------------------------
#define BK 32
#define ROWB 80                      // padded row stride in bytes (32*2 + 16)
#define MAT_B (128 * ROWB)           // 10240 B per matrix per stage
#define STAGE_B (4 * MAT_B)          // 40960 B (Ahi, Alo, Bhi, Blo)
#define NSTAGE 4
#define SMEM_TOTAL (NSTAGE * STAGE_B)  // 163840 B

__device__ __forceinline__ void load_stage(
    uint32_t sb, const __nv_bfloat16* const* src, int kofs, int tid) {
    #pragma unroll
    for (int m = 0; m < 4; ++m) {
        const __nv_bfloat16* s = src[m];
        #pragma unroll
        for (int i = 0; i < 2; ++i) {
            int idx  = tid + 256 * i;
            int row  = idx >> 2;
            int ch   = idx & 3;
            const void* gp = s + (size_t)row * NDIM + kofs + ch * 8;
            uint32_t dp = sb + m * MAT_B + row * ROWB + ch * 16;
            CP_ASYNC16(dp, gp);
        }
    }
    CP_COMMIT();
}

__global__ void __launch_bounds__(256, 1)
srft_gemm_mma(float* __restrict__ out) {
    extern __shared__ __align__(128) char smem[];
    const uint32_t sbase = smem_u32(smem);
    const int tid  = threadIdx.x;
    const int lane = tid & 31;
    const int wid  = tid >> 5;
    const int wm   = wid & 3;        // 4 warps in M
    const int wn   = wid >> 2;       // 2 warps in N
    const int mbase = wm * 32;
    const int nbase = wn * 64;
    const int d0 = blockIdx.x * 128; // M-fast raster: B streamed once
    const int n0 = blockIdx.y * 128;

    const __nv_bfloat16* src[4] = {
        g_Ahi + (size_t)d0 * NDIM, g_Alo + (size_t)d0 * NDIM,
        g_Bhi + (size_t)n0 * NDIM, g_Blo + (size_t)n0 * NDIM };

    float acc[2][8][4];
    #pragma unroll
    for (int i = 0; i < 2; ++i)
        #pragma unroll
        for (int nt = 0; nt < 8; ++nt)
            #pragma unroll
            for (int q = 0; q < 4; ++q) acc[i][nt][q] = 0.0f;

    // prologue: stages 0..2
    #pragma unroll
    for (int s = 0; s < NSTAGE - 1; ++s)
        load_stage(sbase + s * STAGE_B, src, s * BK, tid);

    // precomputed per-lane ldmatrix address components
    const int aRowOff = (lane & 15) * ROWB + (lane >> 4) * 16;
    const int bRowOff = (((lane >> 4) & 1) * 8 + (lane & 7)) * ROWB +
                        ((lane >> 3) & 1) * 16;

    const int NT = NDIM / BK;   // 256
    for (int t = 0; t < NT; ++t) {
        CP_WAIT2();
        __syncthreads();
        if (t + NSTAGE - 1 < NT)
            load_stage(sbase + ((t + NSTAGE - 1) & (NSTAGE - 1)) * STAGE_B,
                       src, (t + NSTAGE - 1) * BK, tid);

        const uint32_t sb = sbase + (t & (NSTAGE - 1)) * STAGE_B;
        #pragma unroll
        for (int j = 0; j < 2; ++j) {           // two k16 steps per stage
            uint32_t a[2][2][4];                // [split][mtile][4]
            #pragma unroll
            for (int h = 0; h < 2; ++h)
                #pragma unroll
                for (int i = 0; i < 2; ++i) {
                    uint32_t ad = sb + h * MAT_B +
                                  (mbase + i * 16) * ROWB + j * 32 + aRowOff;
                    LDSM4(a[h][i][0], a[h][i][1], a[h][i][2], a[h][i][3], ad);
                }
            uint32_t b[2][4][4];                // [split][nb][4]
            #pragma unroll
            for (int h = 0; h < 2; ++h)
                #pragma unroll
                for (int nb = 0; nb < 4; ++nb) {
                    uint32_t bd = sb + (2 + h) * MAT_B +
                                  (nbase + nb * 16) * ROWB + j * 32 + bRowOff;
                    LDSM4(b[h][nb][0], b[h][nb][1], b[h][nb][2], b[h][nb][3], bd);
                }
            #pragma unroll
            for (int i = 0; i < 2; ++i)
                #pragma unroll
                for (int nt = 0; nt < 8; ++nt) {
                    const int nb = nt >> 1, o = (nt & 1) * 2;
                    MMA16816(acc[i][nt], a[0][i], b[0][nb][o], b[0][nb][o + 1]);
                    MMA16816(acc[i][nt], a[0][i], b[1][nb][o], b[1][nb][o + 1]);
                    MMA16816(acc[i][nt], a[1][i], b[0][nb][o], b[0][nb][o + 1]);
                }
        }
    }

    // epilogue: fragment -> GMEM (float2 stores)
    const int r = lane >> 2, c = (lane & 3) * 2;
    #pragma unroll
    for (int i = 0; i < 2; ++i) {
        const int row = d0 + mbase + i * 16 + r;
        #pragma unroll
        for (int nt = 0; nt < 8; ++nt) {
            const int col = n0 + nbase + nt * 8 + c;
            *(float2*)(out + (size_t)row * MC + col) =
                make_float2(acc[i][nt][0], acc[i][nt][1]);
            *(float2*)(out + (size_t)(row + 8) * MC + col) =
                make_float2(acc[i][nt][2], acc[i][nt][3]);
        }
    }
}

// ---------------------------------------------------------------------------
extern "C" void kernel_launch(void* const* d_in, const int* in_sizes, int n_in,
                              void* d_out, int out_size) {
    const float* Mmat = (const float*)d_in[0];
    const float* Dv   = (const float*)d_in[1];
    const int*   Pv   = (const int*)d_in[2];
    float* out = (float*)d_out;

    cudaFuncSetAttribute(srft_gemm_mma,
                         cudaFuncAttributeMaxDynamicSharedMemorySize, SMEM_TOTAL);

    build_AC<<<dim3(NDIM / 256, DSK), 256>>>(Dv, Pv);
    conv_transpose<<<dim3(MC / 32, NDIM / 32), dim3(32, 8)>>>(Mmat);
    srft_gemm_mma<<<dim3(DSK / 128, MC / 128), 256, SMEM_TOTAL>>>(out);
}

// round 5
// speedup vs baseline: 2.2581x; 1.1303x over previous
#include <cuda_runtime.h>
#include <cuda_bf16.h>
#include <cstdint>

#define NDIM 8192   // K
#define DSK  1024   // output rows (M of GEMM)
#define MC   4096   // output cols (N of GEMM)

// ---------------- device scratch (allocation-free rule) ----------------------
__device__ __nv_bfloat16 g_Ahi[(size_t)DSK * NDIM];   // 16 MB
__device__ __nv_bfloat16 g_Alo[(size_t)DSK * NDIM];   // 16 MB
__device__ __nv_bfloat16 g_Bhi[(size_t)MC * NDIM];    // 64 MB (M^T, K-major)
__device__ __nv_bfloat16 g_Blo[(size_t)MC * NDIM];    // 64 MB

// ---------------- helpers ----------------------------------------------------
__device__ __forceinline__ uint32_t smem_u32(const void* p) {
    uint32_t a;
    asm("{ .reg .u64 t; cvta.to.shared.u64 t, %1; cvt.u32.u64 %0, t; }"
        : "=r"(a) : "l"(p));
    return a;
}
#define CP_ASYNC16(dst_u32, src_ptr) \
    asm volatile("cp.async.cg.shared.global [%0], [%1], 16;" \
                 :: "r"(dst_u32), "l"(src_ptr) : "memory")
#define CP_COMMIT() asm volatile("cp.async.commit_group;" ::: "memory")
#define CP_WAIT1()  asm volatile("cp.async.wait_group 1;" ::: "memory")

#define LDSM4(r0, r1, r2, r3, addr) \
    asm volatile("ldmatrix.sync.aligned.m8n8.x4.shared.b16 {%0,%1,%2,%3}, [%4];" \
                 : "=r"(r0), "=r"(r1), "=r"(r2), "=r"(r3) : "r"(addr))

#define MMA16816(c, a, b0, b1) \
    asm volatile("mma.sync.aligned.m16n8k16.row.col.f32.bf16.bf16.f32 " \
                 "{%0,%1,%2,%3}, {%4,%5,%6,%7}, {%8,%9}, {%0,%1,%2,%3};" \
                 : "+f"((c)[0]), "+f"((c)[1]), "+f"((c)[2]), "+f"((c)[3]) \
                 : "r"((a)[0]), "r"((a)[1]), "r"((a)[2]), "r"((a)[3]), \
                   "r"(b0), "r"(b1))

// ---------------------------------------------------------------------------
// Kernel 1: build C' = cos(ang)*w*D  (exact fp32 rounding order of reference)
// ---------------------------------------------------------------------------
__global__ void build_AC(const float* __restrict__ Dv, const int* __restrict__ Pv) {
    const int d = blockIdx.y;
    const int k = blockIdx.x * blockDim.x + threadIdx.x;
    const int n = Pv[d];
    const float c0 = (float)(3.14159265358979323846 / 16384.0);
    float t   = c0 * (float)(2 * n + 1);
    float ang = t * (float)k;
    float w   = (k == 0) ? 6.103515625e-05f : 1.220703125e-04f;
    float c   = cosf(ang) * w * Dv[k];
    __nv_bfloat16 hi = __float2bfloat16(c);
    float lo = c - __bfloat162float(hi);
    size_t o = (size_t)d * NDIM + k;
    g_Ahi[o] = hi;
    g_Alo[o] = __float2bfloat16(lo);
}

// ---------------------------------------------------------------------------
// Kernel 2: transpose+convert M [8192,4096] f32 -> Bt_hi/lo [4096,8192] bf16
// (paired bf16x2 stores: 4B per store instead of 2B)
// ---------------------------------------------------------------------------
__global__ void conv_transpose(const float* __restrict__ Min) {
    __shared__ float tile[32][33];
    const int x0 = blockIdx.x * 32;  // n
    const int y0 = blockIdx.y * 32;  // k
    const int tx = threadIdx.x, ty = threadIdx.y;   // 32 x 8
    #pragma unroll
    for (int j = 0; j < 32; j += 8)
        tile[ty + j][tx] = Min[(size_t)(y0 + ty + j) * MC + x0 + tx];
    __syncthreads();
    #pragma unroll
    for (int jj = 0; jj < 2; ++jj) {
        const int n_loc = 2 * ty + (tx >> 4) + 16 * jj;
        const int kp    = tx & 15;
        float v0 = tile[2 * kp][n_loc];
        float v1 = tile[2 * kp + 1][n_loc];
        __nv_bfloat16 h0 = __float2bfloat16(v0);
        __nv_bfloat16 h1 = __float2bfloat16(v1);
        float l0 = v0 - __bfloat162float(h0);
        float l1 = v1 - __bfloat162float(h1);
        __nv_bfloat162 hh; hh.x = h0; hh.y = h1;
        __nv_bfloat162 ll; ll.x = __float2bfloat16(l0); ll.y = __float2bfloat16(l1);
        size_t o = (size_t)(x0 + n_loc) * NDIM + y0 + 2 * kp;
        *(__nv_bfloat162*)(g_Bhi + o) = hh;
        *(__nv_bfloat162*)(g_Blo + o) = ll;
    }
}

// ---------------------------------------------------------------------------
// Kernel 3: GEMM via mma.sync bf16.  out = Ahi@Bhi + Ahi@Blo + Alo@Bhi
// CTA 128x128, BK=32, 2-stage cp.async pipeline, 80KB smem -> 2 CTAs/SM
// (single wave of 256 CTAs), 8 warps (4M x 2N), warp tile 32x64
// ---------------------------------------------------------------------------
#define BK 32
#define ROWB 80                      // padded row stride in bytes (32*2 + 16)
#define MAT_B (128 * ROWB)           // 10240 B per matrix per stage
#define STAGE_B (4 * MAT_B)          // 40960 B (Ahi, Alo, Bhi, Blo)
#define NSTAGE 2
#define SMEM_TOTAL (NSTAGE * STAGE_B)  // 81920 B

__device__ __forceinline__ void load_stage(
    uint32_t sb, const __nv_bfloat16* const* src, int kofs, int tid) {
    #pragma unroll
    for (int m = 0; m < 4; ++m) {
        const __nv_bfloat16* s = src[m];
        #pragma unroll
        for (int i = 0; i < 2; ++i) {
            int idx  = tid + 256 * i;
            int row  = idx >> 2;
            int ch   = idx & 3;
            const void* gp = s + (size_t)row * NDIM + kofs + ch * 8;
            uint32_t dp = sb + m * MAT_B + row * ROWB + ch * 16;
            CP_ASYNC16(dp, gp);
        }
    }
    CP_COMMIT();
}

__global__ void __launch_bounds__(256, 2)
srft_gemm_mma(float* __restrict__ out) {
    extern __shared__ __align__(128) char smem[];
    const uint32_t sbase = smem_u32(smem);
    const int tid  = threadIdx.x;
    const int lane = tid & 31;
    const int wid  = tid >> 5;
    const int wm   = wid & 3;        // 4 warps in M
    const int wn   = wid >> 2;       // 2 warps in N
    const int mbase = wm * 32;
    const int nbase = wn * 64;
    const int d0 = blockIdx.x * 128; // M-fast raster: B tiles shared via L2
    const int n0 = blockIdx.y * 128;

    const __nv_bfloat16* src[4] = {
        g_Ahi + (size_t)d0 * NDIM, g_Alo + (size_t)d0 * NDIM,
        g_Bhi + (size_t)n0 * NDIM, g_Blo + (size_t)n0 * NDIM };

    float acc[2][8][4];
    #pragma unroll
    for (int i = 0; i < 2; ++i)
        #pragma unroll
        for (int nt = 0; nt < 8; ++nt)
            #pragma unroll
            for (int q = 0; q < 4; ++q) acc[i][nt][q] = 0.0f;

    // prologue: fill both stages
    load_stage(sbase, src, 0, tid);
    load_stage(sbase + STAGE_B, src, BK, tid);

    // per-lane ldmatrix address components (validated in round 4)
    const int aRowOff = (lane & 15) * ROWB + (lane >> 4) * 16;
    const int bRowOff = (((lane >> 4) & 1) * 8 + (lane & 7)) * ROWB +
                        ((lane >> 3) & 1) * 16;

    const int NT = NDIM / BK;   // 256
    for (int t = 0; t < NT; ++t) {
        CP_WAIT1();             // oldest stage landed
        __syncthreads();

        const uint32_t sb = sbase + (t & 1) * STAGE_B;
        #pragma unroll
        for (int j = 0; j < 2; ++j) {           // two k16 steps per stage
            uint32_t a[2][2][4];                // [split][mtile][4]
            #pragma unroll
            for (int h = 0; h < 2; ++h)
                #pragma unroll
                for (int i = 0; i < 2; ++i) {
                    uint32_t ad = sb + h * MAT_B +
                                  (mbase + i * 16) * ROWB + j * 32 + aRowOff;
                    LDSM4(a[h][i][0], a[h][i][1], a[h][i][2], a[h][i][3], ad);
                }
            #pragma unroll
            for (int half = 0; half < 2; ++half) {   // N in two halves
                uint32_t b[2][2][4];            // [split][nb2][4]
                #pragma unroll
                for (int h = 0; h < 2; ++h)
                    #pragma unroll
                    for (int nb2 = 0; nb2 < 2; ++nb2) {
                        int nb = half * 2 + nb2;
                        uint32_t bd = sb + (2 + h) * MAT_B +
                                      (nbase + nb * 16) * ROWB + j * 32 + bRowOff;
                        LDSM4(b[h][nb2][0], b[h][nb2][1],
                              b[h][nb2][2], b[h][nb2][3], bd);
                    }
                #pragma unroll
                for (int i = 0; i < 2; ++i)
                    #pragma unroll
                    for (int nt2 = 0; nt2 < 4; ++nt2) {
                        const int nt = half * 4 + nt2;
                        const int nb2 = nt2 >> 1, o = (nt2 & 1) * 2;
                        MMA16816(acc[i][nt], a[0][i], b[0][nb2][o], b[0][nb2][o + 1]);
                        MMA16816(acc[i][nt], a[0][i], b[1][nb2][o], b[1][nb2][o + 1]);
                        MMA16816(acc[i][nt], a[1][i], b[0][nb2][o], b[0][nb2][o + 1]);
                    }
            }
        }

        __syncthreads();        // all warps done reading this stage
        if (t + 2 < NT)
            load_stage(sb, src, (t + 2) * BK, tid);  // refill the stage just read
    }

    // epilogue: fragment -> GMEM (float2 stores)
    const int r = lane >> 2, c = (lane & 3) * 2;
    #pragma unroll
    for (int i = 0; i < 2; ++i) {
        const int row = d0 + mbase + i * 16 + r;
        #pragma unroll
        for (int nt = 0; nt < 8; ++nt) {
            const int col = n0 + nbase + nt * 8 + c;
            *(float2*)(out + (size_t)row * MC + col) =
                make_float2(acc[i][nt][0], acc[i][nt][1]);
            *(float2*)(out + (size_t)(row + 8) * MC + col) =
                make_float2(acc[i][nt][2], acc[i][nt][3]);
        }
    }
}

// ---------------------------------------------------------------------------
extern "C" void kernel_launch(void* const* d_in, const int* in_sizes, int n_in,
                              void* d_out, int out_size) {
    const float* Mmat = (const float*)d_in[0];
    const float* Dv   = (const float*)d_in[1];
    const int*   Pv   = (const int*)d_in[2];
    float* out = (float*)d_out;

    cudaFuncSetAttribute(srft_gemm_mma,
                         cudaFuncAttributeMaxDynamicSharedMemorySize, SMEM_TOTAL);

    build_AC<<<dim3(NDIM / 256, DSK), 256>>>(Dv, Pv);
    conv_transpose<<<dim3(MC / 32, NDIM / 32), dim3(32, 8)>>>(Mmat);
    srft_gemm_mma<<<dim3(DSK / 128, MC / 128), 256, SMEM_TOTAL>>>(out);
}

// round 6
// speedup vs baseline: 2.2593x; 1.0005x over previous
#include <cuda_runtime.h>
#include <cuda_bf16.h>
#include <cstdint>

#define NDIM 8192   // K
#define DSK  1024   // output rows (M of GEMM)
#define MC   4096   // output cols (N of GEMM)

// ---------------- device scratch (allocation-free rule) ----------------------
__device__ __nv_bfloat16 g_Ahi[(size_t)DSK * NDIM];   // 16 MB
__device__ __nv_bfloat16 g_Alo[(size_t)DSK * NDIM];   // 16 MB
__device__ __nv_bfloat16 g_Bhi[(size_t)MC * NDIM];    // 64 MB (M^T, K-major)
__device__ __nv_bfloat16 g_Blo[(size_t)MC * NDIM];    // 64 MB

// ---------------- helpers ----------------------------------------------------
__device__ __forceinline__ uint32_t smem_u32(const void* p) {
    uint32_t a;
    asm("{ .reg .u64 t; cvta.to.shared.u64 t, %1; cvt.u32.u64 %0, t; }"
        : "=r"(a) : "l"(p));
    return a;
}
#define CP_ASYNC16(dst_u32, src_ptr) \
    asm volatile("cp.async.cg.shared.global [%0], [%1], 16;" \
                 :: "r"(dst_u32), "l"(src_ptr) : "memory")
#define CP_COMMIT() asm volatile("cp.async.commit_group;" ::: "memory")
#define CP_WAIT1()  asm volatile("cp.async.wait_group 1;" ::: "memory")

#define LDSM4(r0, r1, r2, r3, addr) \
    asm volatile("ldmatrix.sync.aligned.m8n8.x4.shared.b16 {%0,%1,%2,%3}, [%4];" \
                 : "=r"(r0), "=r"(r1), "=r"(r2), "=r"(r3) : "r"(addr))

#define MMA16816(c, a, b0, b1) \
    asm volatile("mma.sync.aligned.m16n8k16.row.col.f32.bf16.bf16.f32 " \
                 "{%0,%1,%2,%3}, {%4,%5,%6,%7}, {%8,%9}, {%0,%1,%2,%3};" \
                 : "+f"((c)[0]), "+f"((c)[1]), "+f"((c)[2]), "+f"((c)[3]) \
                 : "r"((a)[0]), "r"((a)[1]), "r"((a)[2]), "r"((a)[3]), \
                   "r"(b0), "r"(b1))

// ---------------------------------------------------------------------------
// Kernel 1 (merged prep): first 32768 blocks build C' hi/lo (exact fp32
// rounding order of the reference), remaining 32768 blocks transpose+convert
// M into K-major bf16 hi/lo.  One kernel -> 2 launches per replay, so ncu's
// "-s 5 -c 1" lands on the GEMM.
// ---------------------------------------------------------------------------
__global__ void __launch_bounds__(256)
prep_all(const float* __restrict__ Min, const float* __restrict__ Dv,
         const int* __restrict__ Pv) {
    const int bid = blockIdx.x;
    const int tid = threadIdx.x;
    if (bid < 32768) {
        // ---- build A (C' matrix) ----
        const int d = bid >> 5;
        const int k = (bid & 31) * 256 + tid;
        const int n = Pv[d];
        const float c0 = (float)(3.14159265358979323846 / 16384.0);
        float t   = c0 * (float)(2 * n + 1);
        float ang = t * (float)k;
        float w   = (k == 0) ? 6.103515625e-05f : 1.220703125e-04f;
        float c   = cosf(ang) * w * Dv[k];
        __nv_bfloat16 hi = __float2bfloat16(c);
        float lo = c - __bfloat162float(hi);
        size_t o = (size_t)d * NDIM + k;
        g_Ahi[o] = hi;
        g_Alo[o] = __float2bfloat16(lo);
    } else {
        // ---- transpose + split M ----
        __shared__ float tile[32][33];
        const int cbid = bid - 32768;
        const int x0 = (cbid & 127) * 32;   // n
        const int y0 = (cbid >> 7) * 32;    // k
        const int tx = tid & 31, ty = tid >> 5;   // 32 x 8
        #pragma unroll
        for (int j = 0; j < 32; j += 8)
            tile[ty + j][tx] = Min[(size_t)(y0 + ty + j) * MC + x0 + tx];
        __syncthreads();
        #pragma unroll
        for (int jj = 0; jj < 2; ++jj) {
            const int n_loc = 2 * ty + (tx >> 4) + 16 * jj;
            const int kp    = tx & 15;
            float v0 = tile[2 * kp][n_loc];
            float v1 = tile[2 * kp + 1][n_loc];
            __nv_bfloat16 h0 = __float2bfloat16(v0);
            __nv_bfloat16 h1 = __float2bfloat16(v1);
            float l0 = v0 - __bfloat162float(h0);
            float l1 = v1 - __bfloat162float(h1);
            __nv_bfloat162 hh; hh.x = h0; hh.y = h1;
            __nv_bfloat162 ll; ll.x = __float2bfloat16(l0); ll.y = __float2bfloat16(l1);
            size_t o = (size_t)(x0 + n_loc) * NDIM + y0 + 2 * kp;
            *(__nv_bfloat162*)(g_Bhi + o) = hh;
            *(__nv_bfloat162*)(g_Blo + o) = ll;
        }
    }
}

// ---------------------------------------------------------------------------
// Kernel 2: GEMM via mma.sync bf16.  out = Ahi@Bhi + Ahi@Blo + Alo@Bhi
// CTA 128x128, BK=32, 2-stage cp.async pipeline, 80KB smem -> 2 CTAs/SM,
// 8 warps (4M x 2N), warp tile 32x64.  MMA issue order puts the 3 split terms
// OUTER so consecutive MMAs hit different accumulators (break RAW chains).
// ---------------------------------------------------------------------------
#define BK 32
#define ROWB 80                      // padded row stride in bytes (32*2 + 16)
#define MAT_B (128 * ROWB)           // 10240 B per matrix per stage
#define STAGE_B (4 * MAT_B)          // 40960 B (Ahi, Alo, Bhi, Blo)
#define NSTAGE 2
#define SMEM_TOTAL (NSTAGE * STAGE_B)  // 81920 B

__device__ __forceinline__ void load_stage(
    uint32_t sb, const __nv_bfloat16* const* src, int kofs, int tid) {
    #pragma unroll
    for (int m = 0; m < 4; ++m) {
        const __nv_bfloat16* s = src[m];
        #pragma unroll
        for (int i = 0; i < 2; ++i) {
            int idx  = tid + 256 * i;
            int row  = idx >> 2;
            int ch   = idx & 3;
            const void* gp = s + (size_t)row * NDIM + kofs + ch * 8;
            uint32_t dp = sb + m * MAT_B + row * ROWB + ch * 16;
            CP_ASYNC16(dp, gp);
        }
    }
    CP_COMMIT();
}

__global__ void __launch_bounds__(256, 2)
srft_gemm_mma(float* __restrict__ out) {
    extern __shared__ __align__(128) char smem[];
    const uint32_t sbase = smem_u32(smem);
    const int tid  = threadIdx.x;
    const int lane = tid & 31;
    const int wid  = tid >> 5;
    const int wm   = wid & 3;        // 4 warps in M
    const int wn   = wid >> 2;       // 2 warps in N
    const int mbase = wm * 32;
    const int nbase = wn * 64;
    const int d0 = blockIdx.x * 128;
    const int n0 = blockIdx.y * 128;

    const __nv_bfloat16* src[4] = {
        g_Ahi + (size_t)d0 * NDIM, g_Alo + (size_t)d0 * NDIM,
        g_Bhi + (size_t)n0 * NDIM, g_Blo + (size_t)n0 * NDIM };

    float acc[2][8][4];
    #pragma unroll
    for (int i = 0; i < 2; ++i)
        #pragma unroll
        for (int nt = 0; nt < 8; ++nt)
            #pragma unroll
            for (int q = 0; q < 4; ++q) acc[i][nt][q] = 0.0f;

    // prologue: fill both stages
    load_stage(sbase, src, 0, tid);
    load_stage(sbase + STAGE_B, src, BK, tid);

    // per-lane ldmatrix address components (validated in round 4)
    const int aRowOff = (lane & 15) * ROWB + (lane >> 4) * 16;
    const int bRowOff = (((lane >> 4) & 1) * 8 + (lane & 7)) * ROWB +
                        ((lane >> 3) & 1) * 16;

    const int NT = NDIM / BK;   // 256
    for (int t = 0; t < NT; ++t) {
        CP_WAIT1();             // oldest stage landed
        __syncthreads();

        const uint32_t sb = sbase + (t & 1) * STAGE_B;
        #pragma unroll
        for (int j = 0; j < 2; ++j) {           // two k16 steps per stage
            uint32_t a[2][2][4];                // [split][mtile][4]
            #pragma unroll
            for (int h = 0; h < 2; ++h)
                #pragma unroll
                for (int i = 0; i < 2; ++i) {
                    uint32_t ad = sb + h * MAT_B +
                                  (mbase + i * 16) * ROWB + j * 32 + aRowOff;
                    LDSM4(a[h][i][0], a[h][i][1], a[h][i][2], a[h][i][3], ad);
                }
            #pragma unroll
            for (int half = 0; half < 2; ++half) {   // N in two halves
                uint32_t b[2][2][4];            // [split][nb2][4]
                #pragma unroll
                for (int h = 0; h < 2; ++h)
                    #pragma unroll
                    for (int nb2 = 0; nb2 < 2; ++nb2) {
                        int nb = half * 2 + nb2;
                        uint32_t bd = sb + (2 + h) * MAT_B +
                                      (nbase + nb * 16) * ROWB + j * 32 + bRowOff;
                        LDSM4(b[h][nb2][0], b[h][nb2][1],
                              b[h][nb2][2], b[h][nb2][3], bd);
                    }
                // term-outer issue order: consecutive MMAs -> 8 distinct accs
                #pragma unroll
                for (int term = 0; term < 3; ++term) {
                    const int ha = (term == 2) ? 1 : 0;   // A split index
                    const int hb = (term == 1) ? 1 : 0;   // B split index
                    #pragma unroll
                    for (int i = 0; i < 2; ++i)
                        #pragma unroll
                        for (int nt2 = 0; nt2 < 4; ++nt2) {
                            const int nt = half * 4 + nt2;
                            const int nb2 = nt2 >> 1, o = (nt2 & 1) * 2;
                            MMA16816(acc[i][nt], a[ha][i],
                                     b[hb][nb2][o], b[hb][nb2][o + 1]);
                        }
                }
            }
        }

        __syncthreads();        // all warps done reading this stage
        if (t + 2 < NT)
            load_stage(sb, src, (t + 2) * BK, tid);  // refill the stage just read
    }

    // epilogue: fragment -> GMEM (float2 stores)
    const int r = lane >> 2, c = (lane & 3) * 2;
    #pragma unroll
    for (int i = 0; i < 2; ++i) {
        const int row = d0 + mbase + i * 16 + r;
        #pragma unroll
        for (int nt = 0; nt < 8; ++nt) {
            const int col = n0 + nbase + nt * 8 + c;
            *(float2*)(out + (size_t)row * MC + col) =
                make_float2(acc[i][nt][0], acc[i][nt][1]);
            *(float2*)(out + (size_t)(row + 8) * MC + col) =
                make_float2(acc[i][nt][2], acc[i][nt][3]);
        }
    }
}

// ---------------------------------------------------------------------------
extern "C" void kernel_launch(void* const* d_in, const int* in_sizes, int n_in,
                              void* d_out, int out_size) {
    const float* Mmat = (const float*)d_in[0];
    const float* Dv   = (const float*)d_in[1];
    const int*   Pv   = (const int*)d_in[2];
    float* out = (float*)d_out;

    cudaFuncSetAttribute(srft_gemm_mma,
                         cudaFuncAttributeMaxDynamicSharedMemorySize, SMEM_TOTAL);

    prep_all<<<65536, 256>>>(Mmat, Dv, Pv);
    srft_gemm_mma<<<dim3(DSK / 128, MC / 128), 256, SMEM_TOTAL>>>(out);
}

// round 7
// speedup vs baseline: 2.5611x; 1.1336x over previous
#include <cuda_runtime.h>
#include <cuda_bf16.h>
#include <cstdint>

#define NDIM 8192   // K
#define DSK  1024   // output rows (M of GEMM)
#define MC   4096   // output cols (N of GEMM)

// ---------------- device scratch (allocation-free rule) ----------------------
__device__ __nv_bfloat16 g_Ahi[(size_t)DSK * NDIM];   // 16 MB
__device__ __nv_bfloat16 g_Alo[(size_t)DSK * NDIM];   // 16 MB
__device__ __nv_bfloat16 g_Bhi[(size_t)MC * NDIM];    // 64 MB (M^T, K-major)
__device__ __nv_bfloat16 g_Blo[(size_t)MC * NDIM];    // 64 MB

// ---------------- helpers ----------------------------------------------------
__device__ __forceinline__ uint32_t smem_u32(const void* p) {
    uint32_t a;
    asm("{ .reg .u64 t; cvta.to.shared.u64 t, %1; cvt.u32.u64 %0, t; }"
        : "=r"(a) : "l"(p));
    return a;
}
#define CP_ASYNC16(dst_u32, src_ptr) \
    asm volatile("cp.async.cg.shared.global [%0], [%1], 16;" \
                 :: "r"(dst_u32), "l"(src_ptr) : "memory")
#define CP_COMMIT() asm volatile("cp.async.commit_group;" ::: "memory")
#define CP_WAIT1()  asm volatile("cp.async.wait_group 1;" ::: "memory")

#define LDSM4(r0, r1, r2, r3, addr) \
    asm volatile("ldmatrix.sync.aligned.m8n8.x4.shared.b16 {%0,%1,%2,%3}, [%4];" \
                 : "=r"(r0), "=r"(r1), "=r"(r2), "=r"(r3) : "r"(addr))

#define MMA16816(c, a, b0, b1) \
    asm volatile("mma.sync.aligned.m16n8k16.row.col.f32.bf16.bf16.f32 " \
                 "{%0,%1,%2,%3}, {%4,%5,%6,%7}, {%8,%9}, {%0,%1,%2,%3};" \
                 : "+f"((c)[0]), "+f"((c)[1]), "+f"((c)[2]), "+f"((c)[3]) \
                 : "r"((a)[0]), "r"((a)[1]), "r"((a)[2]), "r"((a)[3]), \
                   "r"(b0), "r"(b1))

// ---------------------------------------------------------------------------
// Kernel 1 (merged prep): blocks [0,32768) build C' hi/lo (exact fp32 rounding
// order of the reference); blocks [32768,65536) transpose+split M.
// ---------------------------------------------------------------------------
__global__ void __launch_bounds__(256)
prep_all(const float* __restrict__ Min, const float* __restrict__ Dv,
         const int* __restrict__ Pv) {
    const int bid = blockIdx.x;
    const int tid = threadIdx.x;
    if (bid < 32768) {
        const int d = bid >> 5;
        const int k = (bid & 31) * 256 + tid;
        const int n = Pv[d];
        const float c0 = (float)(3.14159265358979323846 / 16384.0);
        float t   = c0 * (float)(2 * n + 1);
        float ang = t * (float)k;
        float w   = (k == 0) ? 6.103515625e-05f : 1.220703125e-04f;
        float c   = cosf(ang) * w * Dv[k];
        __nv_bfloat16 hi = __float2bfloat16(c);
        float lo = c - __bfloat162float(hi);
        size_t o = (size_t)d * NDIM + k;
        g_Ahi[o] = hi;
        g_Alo[o] = __float2bfloat16(lo);
    } else {
        __shared__ float tile[32][33];
        const int cbid = bid - 32768;
        const int x0 = (cbid & 127) * 32;   // n
        const int y0 = (cbid >> 7) * 32;    // k
        const int tx = tid & 31, ty = tid >> 5;   // 32 x 8
        #pragma unroll
        for (int j = 0; j < 32; j += 8)
            tile[ty + j][tx] = Min[(size_t)(y0 + ty + j) * MC + x0 + tx];
        __syncthreads();
        #pragma unroll
        for (int jj = 0; jj < 2; ++jj) {
            const int n_loc = 2 * ty + (tx >> 4) + 16 * jj;
            const int kp    = tx & 15;
            float v0 = tile[2 * kp][n_loc];
            float v1 = tile[2 * kp + 1][n_loc];
            __nv_bfloat16 h0 = __float2bfloat16(v0);
            __nv_bfloat16 h1 = __float2bfloat16(v1);
            float l0 = v0 - __bfloat162float(h0);
            float l1 = v1 - __bfloat162float(h1);
            __nv_bfloat162 hh; hh.x = h0; hh.y = h1;
            __nv_bfloat162 ll; ll.x = __float2bfloat16(l0); ll.y = __float2bfloat16(l1);
            size_t o = (size_t)(x0 + n_loc) * NDIM + y0 + 2 * kp;
            *(__nv_bfloat162*)(g_Bhi + o) = hh;
            *(__nv_bfloat162*)(g_Blo + o) = ll;
        }
    }
}

// ---------------------------------------------------------------------------
// Kernel 2: GEMM via mma.sync bf16.  out = Ahi@Bhi + Ahi@Blo + Alo@Bhi
// CTA 128x128, BK=32, 3-stage cp.async pipeline with ONE __syncthreads per
// K-iteration (CUTLASS sm80 multistage ordering).  Compact 64B rows with
// XOR swizzle (chunk ^= (row>>1)&3): 32KB/stage, 96KB/CTA -> 2 CTAs/SM.
// 8 warps (4M x 2N), warp tile 32x64.
// ---------------------------------------------------------------------------
#define BK 32
#define MAT_B (128 * 64)             // 8192 B per matrix per stage
#define STAGE_B (4 * MAT_B)          // 32768 B (Ahi, Alo, Bhi, Blo)
#define NSTAGE 3
#define SMEM_TOTAL (NSTAGE * STAGE_B)  // 98304 B

__device__ __forceinline__ void load_stage(
    uint32_t sb, const __nv_bfloat16* const* src, int kofs, int tid) {
    #pragma unroll
    for (int m = 0; m < 4; ++m) {
        const __nv_bfloat16* s = src[m];
        #pragma unroll
        for (int i = 0; i < 2; ++i) {
            int idx  = tid + 256 * i;      // 0..511
            int row  = idx >> 2;           // 0..127
            int ch   = idx & 3;            // 16B chunk (k-segment)
            const void* gp = s + (size_t)row * NDIM + kofs + ch * 8;
            uint32_t dp = sb + m * MAT_B + row * 64 +
                          ((ch ^ ((row >> 1) & 3)) * 16);
            CP_ASYNC16(dp, gp);
        }
    }
    CP_COMMIT();
}

__global__ void __launch_bounds__(256, 2)
srft_gemm_mma(float* __restrict__ out) {
    extern __shared__ __align__(128) char smem[];
    const uint32_t sbase = smem_u32(smem);
    const int tid  = threadIdx.x;
    const int lane = tid & 31;
    const int wid  = tid >> 5;
    const int wm   = wid & 3;        // 4 warps in M
    const int wn   = wid >> 2;       // 2 warps in N
    const int mbase = wm * 32;
    const int nbase = wn * 64;
    const int d0 = blockIdx.x * 128;
    const int n0 = blockIdx.y * 128;

    const __nv_bfloat16* src[4] = {
        g_Ahi + (size_t)d0 * NDIM, g_Alo + (size_t)d0 * NDIM,
        g_Bhi + (size_t)n0 * NDIM, g_Blo + (size_t)n0 * NDIM };

    float acc[2][8][4];
    #pragma unroll
    for (int i = 0; i < 2; ++i)
        #pragma unroll
        for (int nt = 0; nt < 8; ++nt)
            #pragma unroll
            for (int q = 0; q < 4; ++q) acc[i][nt][q] = 0.0f;

    // prologue: fill stages 0 and 1
    load_stage(sbase, src, 0, tid);
    load_stage(sbase + STAGE_B, src, BK, tid);

    // per-lane address components (XOR-swizzled 64B rows).
    // Swizzle index is lane-constant: row-base contributions are mult. of 8.
    const int swzA  = ((lane & 15) >> 1) & 3;
    const int aHalf = lane >> 4;                     // 16B half within k16
    const int aBase = (mbase + (lane & 15)) * 64;    // i adds 1024, h adds MAT_B
    const int brow  = ((lane >> 4) & 1) * 8 + (lane & 7);
    const int swzB  = (brow >> 1) & 3;
    const int bHalf = (lane >> 3) & 1;
    const int bBase = (nbase + brow) * 64;           // nb adds 1024

    const int NT = NDIM / BK;   // 256
    int sidx = 0;               // stage index of iteration t
    for (int t = 0; t < NT; ++t) {
        CP_WAIT1();             // stage t landed (<=1 group still in flight)
        __syncthreads();        // also: all warps done with stage t-1

        // refill the stage freed by iteration t-1 with chunk t+2
        if (t + 2 < NT) {
            int fs = sidx + 2; if (fs >= NSTAGE) fs -= NSTAGE;
            load_stage(sbase + fs * STAGE_B, src, (t + 2) * BK, tid);
        }

        const uint32_t sb = sbase + sidx * STAGE_B;
        #pragma unroll
        for (int j = 0; j < 2; ++j) {           // two k16 steps per stage
            uint32_t a[2][2][4];                // [split][mtile][4]
            #pragma unroll
            for (int h = 0; h < 2; ++h)
                #pragma unroll
                for (int i = 0; i < 2; ++i) {
                    uint32_t ad = sb + h * MAT_B + aBase + i * 1024 +
                                  (((2 * j + aHalf) ^ swzA) * 16);
                    LDSM4(a[h][i][0], a[h][i][1], a[h][i][2], a[h][i][3], ad);
                }
            #pragma unroll
            for (int half = 0; half < 2; ++half) {   // N in two halves
                uint32_t b[2][2][4];            // [split][nb2][4]
                #pragma unroll
                for (int h = 0; h < 2; ++h)
                    #pragma unroll
                    for (int nb2 = 0; nb2 < 2; ++nb2) {
                        int nb = half * 2 + nb2;
                        uint32_t bd = sb + (2 + h) * MAT_B + bBase + nb * 1024 +
                                      (((2 * j + bHalf) ^ swzB) * 16);
                        LDSM4(b[h][nb2][0], b[h][nb2][1],
                              b[h][nb2][2], b[h][nb2][3], bd);
                    }
                #pragma unroll
                for (int term = 0; term < 3; ++term) {
                    const int ha = (term == 2) ? 1 : 0;
                    const int hb = (term == 1) ? 1 : 0;
                    #pragma unroll
                    for (int i = 0; i < 2; ++i)
                        #pragma unroll
                        for (int nt2 = 0; nt2 < 4; ++nt2) {
                            const int nt = half * 4 + nt2;
                            const int nb2 = nt2 >> 1, o = (nt2 & 1) * 2;
                            MMA16816(acc[i][nt], a[ha][i],
                                     b[hb][nb2][o], b[hb][nb2][o + 1]);
                        }
                }
            }
        }
        if (++sidx == NSTAGE) sidx = 0;
    }

    // epilogue: fragment -> GMEM (float2 stores)
    const int r = lane >> 2, c = (lane & 3) * 2;
    #pragma unroll
    for (int i = 0; i < 2; ++i) {
        const int row = d0 + mbase + i * 16 + r;
        #pragma unroll
        for (int nt = 0; nt < 8; ++nt) {
            const int col = n0 + nbase + nt * 8 + c;
            *(float2*)(out + (size_t)row * MC + col) =
                make_float2(acc[i][nt][0], acc[i][nt][1]);
            *(float2*)(out + (size_t)(row + 8) * MC + col) =
                make_float2(acc[i][nt][2], acc[i][nt][3]);
        }
    }
}

// ---------------------------------------------------------------------------
extern "C" void kernel_launch(void* const* d_in, const int* in_sizes, int n_in,
                              void* d_out, int out_size) {
    const float* Mmat = (const float*)d_in[0];
    const float* Dv   = (const float*)d_in[1];
    const int*   Pv   = (const int*)d_in[2];
    float* out = (float*)d_out;

    cudaFuncSetAttribute(srft_gemm_mma,
                         cudaFuncAttributeMaxDynamicSharedMemorySize, SMEM_TOTAL);

    prep_all<<<65536, 256>>>(Mmat, Dv, Pv);
    srft_gemm_mma<<<dim3(DSK / 128, MC / 128), 256, SMEM_TOTAL>>>(out);
}